// round 11
// baseline (speedup 1.0000x reference)
#include <cuda_runtime.h>
#include <cuda_fp16.h>
#include <stdint.h>

#define NN 4096
#define DD 70
#define SSTR 72                   // padded row length (floats) in partial buffer
#define KC 64                     // K per chunk
#define KHALF 2048
#define NCH 32                    // chunks per CTA (K-half)
#define MTILE 128
#define TPB 256

// B chunk image: fragment-packed. For (kt 0..3, nt 0..8, lane 0..31):
//   uint4 {bh0, bh1, bl0, bl1} at offset ((kt*9+nt)*32 + lane)*16
#define B_IMG 18432               // 4*9*32*16
#define B_VEC16 (B_IMG / 16)      // 1152
#define SMEM_TOTAL (3 * B_IMG)    // 55296 (triple-buffered B stages)

// ---- device scratch (no allocs allowed) ----
__device__ __align__(16) unsigned char g_sb[64 * B_IMG];     // 1.18 MB, L2-resident
__device__ float g_part[(size_t)2 * 2 * NN * SSTR];          // 9.4 MB partials

__device__ __forceinline__ uint32_t smem_u32(const void* p) {
    uint32_t a;
    asm("{ .reg .u64 t; cvta.to.shared.u64 t, %1; cvt.u32.u64 %0, t; }" : "=r"(a) : "l"(p));
    return a;
}

// split a pair of fp32 into packed fp16x2 hi and lo (residual)
__device__ __forceinline__ void splitA(float x, float y, uint32_t& h, uint32_t& l) {
    __half2 hh = __floats2half2_rn(x, y);
    float2 hf = __half22float2(hh);
    __half2 ll = __floats2half2_rn(x - hf.x, y - hf.y);
    h = *reinterpret_cast<uint32_t*>(&hh);
    l = *reinterpret_cast<uint32_t*>(&ll);
}

__device__ __forceinline__ void mma_f16(float* d, const uint32_t* a, uint32_t b0, uint32_t b1) {
    asm volatile(
        "mma.sync.aligned.m16n8k16.row.col.f32.f16.f16.f32 "
        "{%0,%1,%2,%3}, {%4,%5,%6,%7}, {%8,%9}, {%0,%1,%2,%3};"
        : "+f"(d[0]), "+f"(d[1]), "+f"(d[2]), "+f"(d[3])
        : "r"(a[0]), "r"(a[1]), "r"(a[2]), "r"(a[3]), "r"(b0), "r"(b1));
}

// ---------------- kernel 1: build fragment-packed B images ----------------
// One thread per output uint4. bh0 = fp16x2(s[k0][d], s[k0+1][d]), bh1 = +8 k,
// bl* = fp16 residuals. d = nt*8 + r4 (>=70 -> 0), k0 = c*64 + kt*16 + 2*q4.
__global__ void prep_s_kernel(const float* __restrict__ s) {
    int lane = threadIdx.x;            // 0..31
    int nt   = threadIdx.y;            // 0..8
    int kt   = blockIdx.x;             // 0..3
    int c    = blockIdx.y;             // 0..63
    int r4 = lane >> 2, q4 = lane & 3;
    int d  = nt * 8 + r4;
    int k0 = c * KC + kt * 16 + q4 * 2;
    float s0 = 0.f, s1 = 0.f, s8 = 0.f, s9 = 0.f;
    if (d < DD) {
        s0 = s[(size_t)k0 * DD + d];
        s1 = s[(size_t)(k0 + 1) * DD + d];
        s8 = s[(size_t)(k0 + 8) * DD + d];
        s9 = s[(size_t)(k0 + 9) * DD + d];
    }
    uint32_t h01, l01, h89, l89;
    splitA(s0, s1, h01, l01);
    splitA(s8, s9, h89, l89);
    uint4 v = make_uint4(h01, h89, l01, l89);
    *(uint4*)(g_sb + (size_t)c * B_IMG + ((kt * 9 + nt) * 32 + lane) * 16) = v;
}

// ---------------- kernel 2: split-fp16 mma.sync GEMM, K-split 2 ----------------
// block b: dir = b>>6 (0: s_out row-major A, 1: s_in transposed A),
//          half = (b>>5)&1 (K half), mt = b&31 (128-row tile)
__global__ __launch_bounds__(TPB, 1)
void slayer_mma_kernel(const float* __restrict__ adj)
{
    extern __shared__ unsigned char smem[];
    const uint32_t sb = smem_u32(smem);
    const int tid  = threadIdx.x;
    const int wid  = tid >> 5;
    const int lane = tid & 31;
    const int b    = blockIdx.x;
    const int dir  = b >> 6;
    const int half = (b >> 5) & 1;
    const int mt   = b & 31;
    const int rowbase = mt * MTILE;
    const int kbase   = half * KHALF;
    const int cbase   = half * NCH;
    const bool trans  = (dir == 1);

    const int r4 = lane >> 2;   // 0..7
    const int q4 = lane & 3;    // 0..3
    const int r0 = rowbase + wid * 16 + r4;   // this lane's M row (row 0 of fragment)

    float acc[9][4];
#pragma unroll
    for (int nt = 0; nt < 9; nt++)
#pragma unroll
        for (int u = 0; u < 4; u++) acc[nt][u] = 0.0f;

    // cp.async B stage fill: 1152 uint4, 256 threads -> 4 full + 1 guarded
#define ISSUE_B(ci)                                                             \
    do {                                                                        \
        const unsigned char* src_ = g_sb + (size_t)(cbase + (ci)) * B_IMG;      \
        uint32_t dst_ = sb + (uint32_t)(((ci) % 3) * B_IMG);                    \
        _Pragma("unroll")                                                       \
        for (int u = 0; u < 4; u++) {                                           \
            int t_ = tid + u * TPB;                                             \
            asm volatile("cp.async.cg.shared.global [%0], [%1], 16;"            \
                         :: "r"(dst_ + t_ * 16), "l"(src_ + (size_t)t_ * 16));  \
        }                                                                       \
        if (tid < B_VEC16 - 4 * TPB) {                                          \
            int t_ = tid + 4 * TPB;                                             \
            asm volatile("cp.async.cg.shared.global [%0], [%1], 16;"            \
                         :: "r"(dst_ + t_ * 16), "l"(src_ + (size_t)t_ * 16));  \
        }                                                                       \
    } while (0)
#define CP_COMMIT() asm volatile("cp.async.commit_group;" ::: "memory")
#define CP_WAIT1()  asm volatile("cp.async.wait_group 1;" ::: "memory")

    ISSUE_B(0); CP_COMMIT();
    ISSUE_B(1); CP_COMMIT();

    for (int ci = 0; ci < NCH; ci++) {
        CP_WAIT1();           // group(ci) complete (group ci+1 may still be in flight)
        __syncthreads();      // publish stage ci%3; also: all warps done with MMA(ci-1)
        if (ci + 2 < NCH) ISSUE_B(ci + 2);   // after bar: stage (ci+2)%3 is free
        CP_COMMIT();          // always commit (empty group on tail) to keep counts uniform

        const unsigned char* bstage = smem + (ci % 3) * B_IMG + lane * 16;
        const int kc = kbase + ci * KC;

#pragma unroll
        for (int kt = 0; kt < 4; kt++) {
            // ---- A fragments: load adj directly, channel-sum, split fp16 hi/lo ----
            uint32_t ah[4], al[4];
            const int k0 = kc + kt * 16 + q4 * 2;
            if (!trans) {
                const float4* p0 = (const float4*)(adj + (((size_t)r0) * NN + k0) * 2);
                const float4* p1 = (const float4*)(adj + (((size_t)(r0 + 8)) * NN + k0) * 2);
                float4 f;
                f = p0[0]; splitA(f.x + f.y, f.z + f.w, ah[0], al[0]);   // row r,   k0..k0+1
                f = p1[0]; splitA(f.x + f.y, f.z + f.w, ah[1], al[1]);   // row r+8
                f = p0[4]; splitA(f.x + f.y, f.z + f.w, ah[2], al[2]);   // row r,   k0+8..k0+9
                f = p1[4]; splitA(f.x + f.y, f.z + f.w, ah[3], al[3]);   // row r+8
            } else {
#define LD2(ii, jj) (*(const float2*)(adj + (((size_t)(ii)) * NN + (size_t)(jj)) * 2))
                float2 x, y;
                x = LD2(k0,     r0);     y = LD2(k0 + 1, r0);
                splitA(x.x + x.y, y.x + y.y, ah[0], al[0]);
                x = LD2(k0,     r0 + 8); y = LD2(k0 + 1, r0 + 8);
                splitA(x.x + x.y, y.x + y.y, ah[1], al[1]);
                x = LD2(k0 + 8, r0);     y = LD2(k0 + 9, r0);
                splitA(x.x + x.y, y.x + y.y, ah[2], al[2]);
                x = LD2(k0 + 8, r0 + 8); y = LD2(k0 + 9, r0 + 8);
                splitA(x.x + x.y, y.x + y.y, ah[3], al[3]);
#undef LD2
            }
            // ---- B fragments: one LDS.128 each; 3 products per (kt, nt) ----
#pragma unroll
            for (int nt = 0; nt < 9; nt++) {
                uint4 bf = *(const uint4*)(bstage + (kt * 9 + nt) * 512);
                mma_f16(acc[nt], ah, bf.x, bf.y);   // ah * bh
                mma_f16(acc[nt], al, bf.x, bf.y);   // al * bh
                mma_f16(acc[nt], ah, bf.z, bf.w);   // ah * bl
            }
        }
    }

    // ---- epilogue: write partials (row stride SSTR, padded) ----
    float* pb = g_part +
        (((size_t)(dir * 2 + half) * NN) + r0) * SSTR + q4 * 2;
#pragma unroll
    for (int nt = 0; nt < 9; nt++) {
        *(float2*)(pb + nt * 8)            = make_float2(acc[nt][0], acc[nt][1]);
        *(float2*)(pb + 8 * SSTR + nt * 8) = make_float2(acc[nt][2], acc[nt][3]);
    }
#undef ISSUE_B
#undef CP_COMMIT
#undef CP_WAIT1
}

// ---------------- kernel 3: sum K-halves, write (s_in, s_out) ----------------
__global__ void reduce_kernel(float* __restrict__ out) {
    int e = blockIdx.x * blockDim.x + threadIdx.x;
    if (e >= 2 * NN * DD) return;
    int dirr = e / (NN * DD);
    int rem  = e - dirr * NN * DD;
    int row  = rem / DD;
    int dcol = rem - row * DD;
    const float* p = g_part + ((size_t)(dirr * 2) * NN + row) * SSTR + dcol;
    float v = p[0] + p[(size_t)NN * SSTR];
    size_t ob = (dirr == 1) ? 0 : (size_t)NN * DD;   // dir 1 (trans) = s_in first
    out[ob + (size_t)row * DD + dcol] = v;
}

extern "C" void kernel_launch(void* const* d_in, const int* in_sizes, int n_in,
                              void* d_out, int out_size)
{
    const float* adj = (const float*)d_in[0];
    const float* s   = (const float*)d_in[1];
    float* out       = (float*)d_out;

    static bool attr_done = false;
    if (!attr_done) {
        cudaFuncSetAttribute(slayer_mma_kernel,
                             cudaFuncAttributeMaxDynamicSharedMemorySize, SMEM_TOTAL);
        attr_done = true;
    }

    prep_s_kernel<<<dim3(4, 64), dim3(32, 9)>>>(s);
    slayer_mma_kernel<<<128, TPB, SMEM_TOTAL>>>(adj);
    reduce_kernel<<<(2 * NN * DD + TPB - 1) / TPB, TPB>>>(out);
}

// round 12
// speedup vs baseline: 1.5841x; 1.5841x over previous
#include <cuda_runtime.h>
#include <cuda_fp16.h>
#include <stdint.h>

#define NN 4096
#define DD 70
#define SSTR 72                   // padded row length (floats) in partial buffer
#define KC 64                     // K per chunk
#define KHALF 2048
#define NCH 32                    // chunks per CTA (K-half)
#define MTILE 128
#define TPB 256

// B chunk image: fragment-packed. For (kt 0..3, nt 0..8, lane 0..31):
//   uint4 {bh0, bh1, bl0, bl1} at offset ((kt*9+nt)*32 + lane)*16
#define B_IMG 18432               // 4*9*32*16
#define B_VEC16 (B_IMG / 16)      // 1152
#define SMEM_TOTAL (3 * B_IMG)    // 55296 (triple-buffered B stages)

// ---- device scratch (no allocs allowed) ----
__device__ __align__(16) unsigned char g_sb[64 * B_IMG];     // 1.18 MB, L2-resident
__device__ float g_part[(size_t)2 * 2 * NN * SSTR];          // 9.4 MB partials

__device__ __forceinline__ uint32_t smem_u32(const void* p) {
    uint32_t a;
    asm("{ .reg .u64 t; cvta.to.shared.u64 t, %1; cvt.u32.u64 %0, t; }" : "=r"(a) : "l"(p));
    return a;
}

// split a pair of fp32 into packed fp16x2 hi and lo (residual)
__device__ __forceinline__ void splitA(float x, float y, uint32_t& h, uint32_t& l) {
    __half2 hh = __floats2half2_rn(x, y);
    float2 hf = __half22float2(hh);
    __half2 ll = __floats2half2_rn(x - hf.x, y - hf.y);
    h = *reinterpret_cast<uint32_t*>(&hh);
    l = *reinterpret_cast<uint32_t*>(&ll);
}

__device__ __forceinline__ void mma_f16(float* d, const uint32_t* a, uint32_t b0, uint32_t b1) {
    asm volatile(
        "mma.sync.aligned.m16n8k16.row.col.f32.f16.f16.f32 "
        "{%0,%1,%2,%3}, {%4,%5,%6,%7}, {%8,%9}, {%0,%1,%2,%3};"
        : "+f"(d[0]), "+f"(d[1]), "+f"(d[2]), "+f"(d[3])
        : "r"(a[0]), "r"(a[1]), "r"(a[2]), "r"(a[3]), "r"(b0), "r"(b1));
}

// ---------------- kernel 1: build fragment-packed B images ----------------
__global__ void prep_s_kernel(const float* __restrict__ s) {
    int lane = threadIdx.x;            // 0..31
    int nt   = threadIdx.y;            // 0..8
    int kt   = blockIdx.x;             // 0..3
    int c    = blockIdx.y;             // 0..63
    int r4 = lane >> 2, q4 = lane & 3;
    int d  = nt * 8 + r4;
    int k0 = c * KC + kt * 16 + q4 * 2;
    float s0 = 0.f, s1 = 0.f, s8 = 0.f, s9 = 0.f;
    if (d < DD) {
        s0 = s[(size_t)k0 * DD + d];
        s1 = s[(size_t)(k0 + 1) * DD + d];
        s8 = s[(size_t)(k0 + 8) * DD + d];
        s9 = s[(size_t)(k0 + 9) * DD + d];
    }
    uint32_t h01, l01, h89, l89;
    splitA(s0, s1, h01, l01);
    splitA(s8, s9, h89, l89);
    uint4 v = make_uint4(h01, h89, l01, l89);
    *(uint4*)(g_sb + (size_t)c * B_IMG + ((kt * 9 + nt) * 32 + lane) * 16) = v;
}

// ---------------- kernel 2: split-fp16 mma.sync GEMM, chunk-pipelined A ----------------
// block b: dir = b>>6 (0: s_out row-major A, 1: s_in transposed A),
//          half = (b>>5)&1 (K half), mt = b&31 (128-row tile)
__global__ __launch_bounds__(TPB, 1)
void slayer_mma_kernel(const float* __restrict__ adj)
{
    extern __shared__ unsigned char smem[];
    const uint32_t sb = smem_u32(smem);
    const int tid  = threadIdx.x;
    const int wid  = tid >> 5;
    const int lane = tid & 31;
    const int b    = blockIdx.x;
    const int dir  = b >> 6;
    const int half = (b >> 5) & 1;
    const int mt   = b & 31;
    const int rowbase = mt * MTILE;
    const int kbase   = half * KHALF;
    const int cbase   = half * NCH;
    const bool trans  = (dir == 1);

    const int r4 = lane >> 2;   // 0..7
    const int q4 = lane & 3;    // 0..3
    const int r0 = rowbase + wid * 16 + r4;   // this lane's M row (row 0 of fragment)

    float acc[9][4];
#pragma unroll
    for (int nt = 0; nt < 9; nt++)
#pragma unroll
        for (int u = 0; u < 4; u++) acc[nt][u] = 0.0f;

    float praw[64];              // raw A prefetch for next chunk (consumed a chunk later)
    uint32_t afh[16], afl[16];   // converted A fragments for CURRENT chunk: [kt*4+u]

    // ---- A prefetch: raw adj values for chunk ci into praw ----
#define PREF_A(ci)                                                              \
    do {                                                                        \
        const int kc_ = kbase + (ci) * KC;                                      \
        if (!trans) {                                                           \
            _Pragma("unroll")                                                   \
            for (int kt = 0; kt < 4; kt++) {                                    \
                const int k0_ = kc_ + kt * 16 + q4 * 2;                         \
                const float4* p0 = (const float4*)(adj + (((size_t)r0) * NN + k0_) * 2);      \
                const float4* p1 = (const float4*)(adj + (((size_t)(r0 + 8)) * NN + k0_) * 2);\
                float4 f;                                                       \
                f = p0[0]; praw[kt*16+ 0]=f.x; praw[kt*16+ 1]=f.y; praw[kt*16+ 2]=f.z; praw[kt*16+ 3]=f.w; \
                f = p1[0]; praw[kt*16+ 4]=f.x; praw[kt*16+ 5]=f.y; praw[kt*16+ 6]=f.z; praw[kt*16+ 7]=f.w; \
                f = p0[4]; praw[kt*16+ 8]=f.x; praw[kt*16+ 9]=f.y; praw[kt*16+10]=f.z; praw[kt*16+11]=f.w; \
                f = p1[4]; praw[kt*16+12]=f.x; praw[kt*16+13]=f.y; praw[kt*16+14]=f.z; praw[kt*16+15]=f.w; \
            }                                                                   \
        } else {                                                                \
            _Pragma("unroll")                                                   \
            for (int kt = 0; kt < 4; kt++) {                                    \
                const int k0_ = kc_ + kt * 16 + q4 * 2;                         \
                float2 f;                                                       \
                _Pragma("unroll")                                               \
                for (int u = 0; u < 8; u++) {                                   \
                    const int ki = k0_ + (u >> 2) * 8 + (u & 1);                \
                    const int ji = r0 + ((u >> 1) & 1) * 8;                     \
                    f = *(const float2*)(adj + (((size_t)ki) * NN + ji) * 2);   \
                    praw[kt*16 + 2*u]     = f.x;                                \
                    praw[kt*16 + 2*u + 1] = f.y;                                \
                }                                                               \
            }                                                                   \
        }                                                                       \
    } while (0)

    // ---- convert praw -> fragment registers (channel-sum + split fp16 hi/lo) ----
#define CONV_A()                                                                \
    do {                                                                        \
        if (!trans) {                                                           \
            _Pragma("unroll")                                                   \
            for (int kt = 0; kt < 4; kt++) {                                    \
                _Pragma("unroll")                                               \
                for (int u = 0; u < 4; u++) {                                   \
                    const float* f = praw + kt * 16 + u * 4;                    \
                    splitA(f[0] + f[1], f[2] + f[3], afh[kt*4+u], afl[kt*4+u]); \
                }                                                               \
            }                                                                   \
        } else {                                                                \
            _Pragma("unroll")                                                   \
            for (int kt = 0; kt < 4; kt++) {                                    \
                const float* f = praw + kt * 16;                                \
                /* u layout: pairs (k,k+1) for rows r0 / r0+8 / cols +8 */      \
                splitA(f[0]+f[1],   f[2]+f[3],   afh[kt*4+0], afl[kt*4+0]);     \
                splitA(f[4]+f[5],   f[6]+f[7],   afh[kt*4+1], afl[kt*4+1]);     \
                splitA(f[8]+f[9],   f[10]+f[11], afh[kt*4+2], afl[kt*4+2]);     \
                splitA(f[12]+f[13], f[14]+f[15], afh[kt*4+3], afl[kt*4+3]);     \
            }                                                                   \
        }                                                                       \
    } while (0)

    // cp.async B stage fill: 1152 uint4, 256 threads -> 4 full + 1 guarded
#define ISSUE_B(ci)                                                             \
    do {                                                                        \
        const unsigned char* src_ = g_sb + (size_t)(cbase + (ci)) * B_IMG;      \
        uint32_t dst_ = sb + (uint32_t)(((ci) % 3) * B_IMG);                    \
        _Pragma("unroll")                                                       \
        for (int u = 0; u < 4; u++) {                                           \
            int t_ = tid + u * TPB;                                             \
            asm volatile("cp.async.cg.shared.global [%0], [%1], 16;"            \
                         :: "r"(dst_ + t_ * 16), "l"(src_ + (size_t)t_ * 16));  \
        }                                                                       \
        if (tid < B_VEC16 - 4 * TPB) {                                          \
            int t_ = tid + 4 * TPB;                                             \
            asm volatile("cp.async.cg.shared.global [%0], [%1], 16;"            \
                         :: "r"(dst_ + t_ * 16), "l"(src_ + (size_t)t_ * 16));  \
        }                                                                       \
    } while (0)
#define CP_COMMIT() asm volatile("cp.async.commit_group;" ::: "memory")
#define CP_WAIT1()  asm volatile("cp.async.wait_group 1;" ::: "memory")

    // ---- prologue ----
    ISSUE_B(0); CP_COMMIT();
    ISSUE_B(1); CP_COMMIT();
    PREF_A(0);
    CONV_A();            // chunk 0 fragments ready
    PREF_A(1);           // in flight; consumed after chunk 0's MMAs

    for (int ci = 0; ci < NCH; ci++) {
        CP_WAIT1();           // B group(ci) complete
        __syncthreads();      // publish stage ci%3; all warps done reading stage (ci+2)%3
        if (ci + 2 < NCH) ISSUE_B(ci + 2);
        CP_COMMIT();          // uniform group count (empty on tail)

        const unsigned char* bstage = smem + (ci % 3) * B_IMG + lane * 16;

        // ---- MMA: 4 kt x 9 nt x 3 products, fragments already in registers ----
#pragma unroll
        for (int kt = 0; kt < 4; kt++) {
            const uint32_t* ah = afh + kt * 4;
            const uint32_t* al = afl + kt * 4;
#pragma unroll
            for (int nt = 0; nt < 9; nt++) {
                uint4 bf = *(const uint4*)(bstage + (kt * 9 + nt) * 512);
                mma_f16(acc[nt], ah, bf.x, bf.y);   // ah * bh
                mma_f16(acc[nt], al, bf.x, bf.y);   // al * bh
                mma_f16(acc[nt], ah, bf.z, bf.w);   // ah * bl
            }
        }

        // ---- pipeline turn: convert prefetched chunk ci+1, prefetch ci+2 ----
        if (ci + 1 < NCH) {
            CONV_A();
            if (ci + 2 < NCH) PREF_A(ci + 2);
        }
    }

    // ---- epilogue: write partials (row stride SSTR, padded) ----
    float* pb = g_part +
        (((size_t)(dir * 2 + half) * NN) + r0) * SSTR + q4 * 2;
#pragma unroll
    for (int nt = 0; nt < 9; nt++) {
        *(float2*)(pb + nt * 8)            = make_float2(acc[nt][0], acc[nt][1]);
        *(float2*)(pb + 8 * SSTR + nt * 8) = make_float2(acc[nt][2], acc[nt][3]);
    }
#undef PREF_A
#undef CONV_A
#undef ISSUE_B
#undef CP_COMMIT
#undef CP_WAIT1
}

// ---------------- kernel 3: sum K-halves, write (s_in, s_out) ----------------
__global__ void reduce_kernel(float* __restrict__ out) {
    int e = blockIdx.x * blockDim.x + threadIdx.x;
    if (e >= 2 * NN * DD) return;
    int dirr = e / (NN * DD);
    int rem  = e - dirr * NN * DD;
    int row  = rem / DD;
    int dcol = rem - row * DD;
    const float* p = g_part + ((size_t)(dirr * 2) * NN + row) * SSTR + dcol;
    float v = p[0] + p[(size_t)NN * SSTR];
    size_t ob = (dirr == 1) ? 0 : (size_t)NN * DD;   // dir 1 (trans) = s_in first
    out[ob + (size_t)row * DD + dcol] = v;
}

extern "C" void kernel_launch(void* const* d_in, const int* in_sizes, int n_in,
                              void* d_out, int out_size)
{
    const float* adj = (const float*)d_in[0];
    const float* s   = (const float*)d_in[1];
    float* out       = (float*)d_out;

    static bool attr_done = false;
    if (!attr_done) {
        cudaFuncSetAttribute(slayer_mma_kernel,
                             cudaFuncAttributeMaxDynamicSharedMemorySize, SMEM_TOTAL);
        attr_done = true;
    }

    prep_s_kernel<<<dim3(4, 64), dim3(32, 9)>>>(s);
    slayer_mma_kernel<<<128, TPB, SMEM_TOTAL>>>(adj);
    reduce_kernel<<<(2 * NN * DD + TPB - 1) / TPB, TPB>>>(out);
}

// round 13
// speedup vs baseline: 1.8454x; 1.1649x over previous
#include <cuda_runtime.h>
#include <cuda_fp16.h>
#include <stdint.h>

#define NN 4096
#define DD 70
#define SSTR 72                   // padded row length (floats) in partial buffer
#define KC 64                     // K per chunk
#define KHALF 2048
#define NCH 32                    // chunks per CTA (K-half)
#define MTILE 128
#define TPB 256

// B chunk image: fragment-packed fp16 (hi only). For (kt 0..3, nt 0..8, lane 0..31):
//   uint2 {bh0, bh1} at offset ((kt*9+nt)*32 + lane)*8
#define B_IMG 9216                // 4*9*32*8
#define B_VEC16 (B_IMG / 16)      // 576
#define SMEM_TOTAL (3 * B_IMG)    // 27648 (triple-buffered B stages)

// ---- device scratch (no allocs allowed) ----
__device__ __align__(16) unsigned char g_sb[64 * B_IMG];     // 590 KB, L2-resident
__device__ float g_part[(size_t)2 * 2 * NN * SSTR];          // 9.4 MB partials

__device__ __forceinline__ uint32_t smem_u32(const void* p) {
    uint32_t a;
    asm("{ .reg .u64 t; cvta.to.shared.u64 t, %1; cvt.u32.u64 %0, t; }" : "=r"(a) : "l"(p));
    return a;
}

// split a pair of fp32 into packed fp16x2 hi and lo (residual)
__device__ __forceinline__ void splitA(float x, float y, uint32_t& h, uint32_t& l) {
    __half2 hh = __floats2half2_rn(x, y);
    float2 hf = __half22float2(hh);
    __half2 ll = __floats2half2_rn(x - hf.x, y - hf.y);
    h = *reinterpret_cast<uint32_t*>(&hh);
    l = *reinterpret_cast<uint32_t*>(&ll);
}
// hi-only fp16 pack (for B)
__device__ __forceinline__ uint32_t packH(float x, float y) {
    __half2 hh = __floats2half2_rn(x, y);
    return *reinterpret_cast<uint32_t*>(&hh);
}

__device__ __forceinline__ void mma_f16(float* d, const uint32_t* a, uint32_t b0, uint32_t b1) {
    asm volatile(
        "mma.sync.aligned.m16n8k16.row.col.f32.f16.f16.f32 "
        "{%0,%1,%2,%3}, {%4,%5,%6,%7}, {%8,%9}, {%0,%1,%2,%3};"
        : "+f"(d[0]), "+f"(d[1]), "+f"(d[2]), "+f"(d[3])
        : "r"(a[0]), "r"(a[1]), "r"(a[2]), "r"(a[3]), "r"(b0), "r"(b1));
}

// ---------------- kernel 1: build fragment-packed B images (fp16 hi only) ----------------
__global__ void prep_s_kernel(const float* __restrict__ s) {
    int lane = threadIdx.x;            // 0..31
    int nt   = threadIdx.y;            // 0..8
    int kt   = blockIdx.x;             // 0..3
    int c    = blockIdx.y;             // 0..63
    int r4 = lane >> 2, q4 = lane & 3;
    int d  = nt * 8 + r4;
    int k0 = c * KC + kt * 16 + q4 * 2;
    float s0 = 0.f, s1 = 0.f, s8 = 0.f, s9 = 0.f;
    if (d < DD) {
        s0 = s[(size_t)k0 * DD + d];
        s1 = s[(size_t)(k0 + 1) * DD + d];
        s8 = s[(size_t)(k0 + 8) * DD + d];
        s9 = s[(size_t)(k0 + 9) * DD + d];
    }
    uint2 v = make_uint2(packH(s0, s1), packH(s8, s9));
    *(uint2*)(g_sb + (size_t)c * B_IMG + ((kt * 9 + nt) * 32 + lane) * 8) = v;
}

// ---------------- kernel 2: split-fp16 mma.sync GEMM, chunk-pipelined A ----------------
// block b: dir = b>>6 (0: s_out row-major A, 1: s_in transposed A),
//          half = (b>>5)&1 (K half), mt = b&31 (128-row tile)
__global__ __launch_bounds__(TPB, 1)
void slayer_mma_kernel(const float* __restrict__ adj)
{
    extern __shared__ unsigned char smem[];
    const uint32_t sb = smem_u32(smem);
    const int tid  = threadIdx.x;
    const int wid  = tid >> 5;
    const int lane = tid & 31;
    const int b    = blockIdx.x;
    const int dir  = b >> 6;
    const int half = (b >> 5) & 1;
    const int mt   = b & 31;
    const int rowbase = mt * MTILE;
    const int kbase   = half * KHALF;
    const int cbase   = half * NCH;
    const bool trans  = (dir == 1);

    const int r4 = lane >> 2;   // 0..7
    const int q4 = lane & 3;    // 0..3
    const int r0 = rowbase + wid * 16 + r4;   // this lane's M row (row 0 of fragment)

    float acc[9][4];
#pragma unroll
    for (int nt = 0; nt < 9; nt++)
#pragma unroll
        for (int u = 0; u < 4; u++) acc[nt][u] = 0.0f;

    float praw[64];              // raw A prefetch for next chunk (consumed a chunk later)
    uint32_t afh[16], afl[16];   // converted A fragments for CURRENT chunk: [kt*4+u]

    // ---- A prefetch: raw adj values for chunk ci into praw ----
#define PREF_A(ci)                                                              \
    do {                                                                        \
        const int kc_ = kbase + (ci) * KC;                                      \
        if (!trans) {                                                           \
            _Pragma("unroll")                                                   \
            for (int kt = 0; kt < 4; kt++) {                                    \
                const int k0_ = kc_ + kt * 16 + q4 * 2;                         \
                const float4* p0 = (const float4*)(adj + (((size_t)r0) * NN + k0_) * 2);      \
                const float4* p1 = (const float4*)(adj + (((size_t)(r0 + 8)) * NN + k0_) * 2);\
                float4 f;                                                       \
                f = p0[0]; praw[kt*16+ 0]=f.x; praw[kt*16+ 1]=f.y; praw[kt*16+ 2]=f.z; praw[kt*16+ 3]=f.w; \
                f = p1[0]; praw[kt*16+ 4]=f.x; praw[kt*16+ 5]=f.y; praw[kt*16+ 6]=f.z; praw[kt*16+ 7]=f.w; \
                f = p0[4]; praw[kt*16+ 8]=f.x; praw[kt*16+ 9]=f.y; praw[kt*16+10]=f.z; praw[kt*16+11]=f.w; \
                f = p1[4]; praw[kt*16+12]=f.x; praw[kt*16+13]=f.y; praw[kt*16+14]=f.z; praw[kt*16+15]=f.w; \
            }                                                                   \
        } else {                                                                \
            _Pragma("unroll")                                                   \
            for (int kt = 0; kt < 4; kt++) {                                    \
                const int k0_ = kc_ + kt * 16 + q4 * 2;                         \
                float2 f;                                                       \
                _Pragma("unroll")                                               \
                for (int u = 0; u < 8; u++) {                                   \
                    const int ki = k0_ + (u >> 2) * 8 + (u & 1);                \
                    const int ji = r0 + ((u >> 1) & 1) * 8;                     \
                    f = *(const float2*)(adj + (((size_t)ki) * NN + ji) * 2);   \
                    praw[kt*16 + 2*u]     = f.x;                                \
                    praw[kt*16 + 2*u + 1] = f.y;                                \
                }                                                               \
            }                                                                   \
        }                                                                       \
    } while (0)

    // ---- convert praw -> fragment registers (channel-sum + split fp16 hi/lo) ----
#define CONV_A()                                                                \
    do {                                                                        \
        if (!trans) {                                                           \
            _Pragma("unroll")                                                   \
            for (int kt = 0; kt < 4; kt++) {                                    \
                _Pragma("unroll")                                               \
                for (int u = 0; u < 4; u++) {                                   \
                    const float* f = praw + kt * 16 + u * 4;                    \
                    splitA(f[0] + f[1], f[2] + f[3], afh[kt*4+u], afl[kt*4+u]); \
                }                                                               \
            }                                                                   \
        } else {                                                                \
            _Pragma("unroll")                                                   \
            for (int kt = 0; kt < 4; kt++) {                                    \
                const float* f = praw + kt * 16;                                \
                splitA(f[0]+f[1],   f[2]+f[3],   afh[kt*4+0], afl[kt*4+0]);     \
                splitA(f[4]+f[5],   f[6]+f[7],   afh[kt*4+1], afl[kt*4+1]);     \
                splitA(f[8]+f[9],   f[10]+f[11], afh[kt*4+2], afl[kt*4+2]);     \
                splitA(f[12]+f[13], f[14]+f[15], afh[kt*4+3], afl[kt*4+3]);     \
            }                                                                   \
        }                                                                       \
    } while (0)

    // cp.async B stage fill: 576 uint4, 256 threads -> 2 full + 1 guarded
#define ISSUE_B(ci)                                                             \
    do {                                                                        \
        const unsigned char* src_ = g_sb + (size_t)(cbase + (ci)) * B_IMG;      \
        uint32_t dst_ = sb + (uint32_t)(((ci) % 3) * B_IMG);                    \
        _Pragma("unroll")                                                       \
        for (int u = 0; u < 2; u++) {                                           \
            int t_ = tid + u * TPB;                                             \
            asm volatile("cp.async.cg.shared.global [%0], [%1], 16;"            \
                         :: "r"(dst_ + t_ * 16), "l"(src_ + (size_t)t_ * 16));  \
        }                                                                       \
        if (tid < B_VEC16 - 2 * TPB) {                                          \
            int t_ = tid + 2 * TPB;                                             \
            asm volatile("cp.async.cg.shared.global [%0], [%1], 16;"            \
                         :: "r"(dst_ + t_ * 16), "l"(src_ + (size_t)t_ * 16));  \
        }                                                                       \
    } while (0)
#define CP_COMMIT() asm volatile("cp.async.commit_group;" ::: "memory")
#define CP_WAIT1()  asm volatile("cp.async.wait_group 1;" ::: "memory")

    // ---- prologue ----
    ISSUE_B(0); CP_COMMIT();
    ISSUE_B(1); CP_COMMIT();
    PREF_A(0);
    CONV_A();            // chunk 0 fragments ready
    PREF_A(1);           // in flight; consumed after chunk 0's MMAs

    for (int ci = 0; ci < NCH; ci++) {
        CP_WAIT1();           // B group(ci) complete
        __syncthreads();      // publish stage ci%3; all warps done reading stage (ci+2)%3
        if (ci + 2 < NCH) ISSUE_B(ci + 2);
        CP_COMMIT();          // uniform group count (empty on tail)

        const unsigned char* bstage = smem + (ci % 3) * B_IMG + lane * 8;

        // ---- MMA: 4 kt x 9 nt x 2 products (ah*bh + al*bh) ----
#pragma unroll
        for (int kt = 0; kt < 4; kt++) {
            const uint32_t* ah = afh + kt * 4;
            const uint32_t* al = afl + kt * 4;
#pragma unroll
            for (int nt = 0; nt < 9; nt++) {
                uint2 bf = *(const uint2*)(bstage + (kt * 9 + nt) * 256);
                mma_f16(acc[nt], ah, bf.x, bf.y);   // ah * bh
                mma_f16(acc[nt], al, bf.x, bf.y);   // al * bh
            }
        }

        // ---- pipeline turn: convert prefetched chunk ci+1, prefetch ci+2 ----
        if (ci + 1 < NCH) {
            CONV_A();
            if (ci + 2 < NCH) PREF_A(ci + 2);
        }
    }

    // ---- epilogue: write partials (row stride SSTR, padded) ----
    float* pb = g_part +
        (((size_t)(dir * 2 + half) * NN) + r0) * SSTR + q4 * 2;
#pragma unroll
    for (int nt = 0; nt < 9; nt++) {
        *(float2*)(pb + nt * 8)            = make_float2(acc[nt][0], acc[nt][1]);
        *(float2*)(pb + 8 * SSTR + nt * 8) = make_float2(acc[nt][2], acc[nt][3]);
    }
#undef PREF_A
#undef CONV_A
#undef ISSUE_B
#undef CP_COMMIT
#undef CP_WAIT1
}

// ---------------- kernel 3: sum K-halves, write (s_in, s_out) ----------------
__global__ void reduce_kernel(float* __restrict__ out) {
    int e = blockIdx.x * blockDim.x + threadIdx.x;
    if (e >= 2 * NN * DD) return;
    int dirr = e / (NN * DD);
    int rem  = e - dirr * NN * DD;
    int row  = rem / DD;
    int dcol = rem - row * DD;
    const float* p = g_part + ((size_t)(dirr * 2) * NN + row) * SSTR + dcol;
    float v = p[0] + p[(size_t)NN * SSTR];
    size_t ob = (dirr == 1) ? 0 : (size_t)NN * DD;   // dir 1 (trans) = s_in first
    out[ob + (size_t)row * DD + dcol] = v;
}

extern "C" void kernel_launch(void* const* d_in, const int* in_sizes, int n_in,
                              void* d_out, int out_size)
{
    const float* adj = (const float*)d_in[0];
    const float* s   = (const float*)d_in[1];
    float* out       = (float*)d_out;

    static bool attr_done = false;
    if (!attr_done) {
        cudaFuncSetAttribute(slayer_mma_kernel,
                             cudaFuncAttributeMaxDynamicSharedMemorySize, SMEM_TOTAL);
        attr_done = true;
    }

    prep_s_kernel<<<dim3(4, 64), dim3(32, 9)>>>(s);
    slayer_mma_kernel<<<128, TPB, SMEM_TOTAL>>>(adj);
    reduce_kernel<<<(2 * NN * DD + TPB - 1) / TPB, TPB>>>(out);
}